// round 3
// baseline (speedup 1.0000x reference)
#include <cuda_runtime.h>
#include <cuda_bf16.h>
#include <cstdint>
#include <math.h>

// ---------------- problem constants (fixed by setup_inputs) ----------------
#define NT    21
#define S_SP  1560          // N_h*N_w = 30*52
#define NTS   32760         // NT * S_SP
#define DIM   1536
#define ENC   768
#define NA    32
#define NHEAD 12
#define HD    128
#define KVN   3072          // 2*DIM

// ---------------- scratch (static device globals; no allocs allowed) -------
__device__ float g_mm[4];                      // min0,max0,min1,max1
__device__ float g_ct[NTS * 64];               // cos table per (token, freq)
__device__ float g_st[NTS * 64];               // sin table
__device__ float g_q[(size_t)NTS * DIM];       // q after GEMM+RoPE
__device__ float g_kv[(size_t)NT * NA * KVN];  // kv after GEMM (+k RoPE)
__device__ float g_attn[(size_t)NTS * DIM];    // attention output

// ---------------- helpers ----------------
__device__ __forceinline__ uint32_t f2tf32(float f) {
    uint32_t r;
    asm("cvt.rna.tf32.f32 %0, %1;" : "=r"(r) : "f"(f));
    return r;
}

__device__ __forceinline__ void mma_tf32(float* d, const uint32_t* a, const uint32_t* b) {
    asm volatile(
        "mma.sync.aligned.m16n8k8.row.col.f32.tf32.tf32.f32 "
        "{%0,%1,%2,%3}, {%4,%5,%6,%7}, {%8,%9}, {%0,%1,%2,%3};\n"
        : "+f"(d[0]), "+f"(d[1]), "+f"(d[2]), "+f"(d[3])
        : "r"(a[0]), "r"(a[1]), "r"(a[2]), "r"(a[3]), "r"(b[0]), "r"(b[1]));
}

// ---------------- kernel 1: min/max of the two attn-map rows ----------------
__global__ void minmax_kernel(const float* __restrict__ m, int n) {
    const int tid = threadIdx.x, lane = tid & 31, warp = tid >> 5;
    float mn0 = 1e30f, mx0 = -1e30f, mn1 = 1e30f, mx1 = -1e30f;
    for (int i = tid; i < n; i += blockDim.x) {
        float a = m[i], b = m[n + i];
        mn0 = fminf(mn0, a); mx0 = fmaxf(mx0, a);
        mn1 = fminf(mn1, b); mx1 = fmaxf(mx1, b);
    }
    #pragma unroll
    for (int o = 16; o > 0; o >>= 1) {
        mn0 = fminf(mn0, __shfl_xor_sync(0xffffffffu, mn0, o));
        mx0 = fmaxf(mx0, __shfl_xor_sync(0xffffffffu, mx0, o));
        mn1 = fminf(mn1, __shfl_xor_sync(0xffffffffu, mn1, o));
        mx1 = fmaxf(mx1, __shfl_xor_sync(0xffffffffu, mx1, o));
    }
    __shared__ float s0[32], s1[32], s2[32], s3[32];
    if (lane == 0) { s0[warp] = mn0; s1[warp] = mx0; s2[warp] = mn1; s3[warp] = mx1; }
    __syncthreads();
    if (warp == 0) {
        int nw = blockDim.x >> 5;
        mn0 = (lane < nw) ? s0[lane] : 1e30f;
        mx0 = (lane < nw) ? s1[lane] : -1e30f;
        mn1 = (lane < nw) ? s2[lane] : 1e30f;
        mx1 = (lane < nw) ? s3[lane] : -1e30f;
        #pragma unroll
        for (int o = 16; o > 0; o >>= 1) {
            mn0 = fminf(mn0, __shfl_xor_sync(0xffffffffu, mn0, o));
            mx0 = fmaxf(mx0, __shfl_xor_sync(0xffffffffu, mx0, o));
            mn1 = fminf(mn1, __shfl_xor_sync(0xffffffffu, mn1, o));
            mx1 = fmaxf(mx1, __shfl_xor_sync(0xffffffffu, mx1, o));
        }
        if (lane == 0) { g_mm[0] = mn0; g_mm[1] = mx0; g_mm[2] = mn1; g_mm[3] = mx1; }
    }
}

// ---------------- kernel 2: per-(token,freq) cos/sin table ----------------
__global__ void table_kernel(const float* __restrict__ m, int n) {
    int idx = blockIdx.x * blockDim.x + threadIdx.x;
    if (idx >= n * 64) return;
    int t = idx >> 6, i = idx & 63;
    float mn0 = g_mm[0], mx0 = g_mm[1], mn1 = g_mm[2], mx1 = g_mm[3];
    float m0 = m[t], m1 = m[n + t];
    // human1 -> [0,4], human2 -> [20,24]; argmax over 2 rows (first-wins ties)
    float h1 = (m0 - mn0) / (mx0 - mn0 + 1e-8f) * 4.0f;
    float h2 = (m1 - mn1) / (mx1 - mn1 + 1e-8f) * 4.0f + 20.0f;
    float pos = (m0 >= m1) ? h1 : h2;
    float freq = expf(-(float)i * (2.0f / 128.0f) * 9.210340371976184f); // 10000^(-2i/128)
    float s, c;
    sincosf(pos * freq, &s, &c);
    g_ct[idx] = c;
    g_st[idx] = s;
}

// ---------------- TF32 GEMM:  C[M,N] = A[M,K] @ B[N,K]^T + bias, + epilogue -
// EPI: 0 = bias only, 1 = bias + per-token RoPE (q), 2 = bias + bucket RoPE on k half (kv)
#define SMEM_BYTES (2 * 2 * 128 * 32 * 4)   // double-buffered A & B tiles = 64KB

template <int EPI>
__global__ __launch_bounds__(256)
void gemm_tf32(const float* __restrict__ A, const float* __restrict__ B,
               const float* __restrict__ bias, float* __restrict__ C,
               int M, int N, int K) {
    extern __shared__ float sm[];
    float* As = sm;             // 2 * 4096 floats
    float* Bs = sm + 2 * 4096;  // 2 * 4096 floats

    const int tid = threadIdx.x, lane = tid & 31, warp = tid >> 5;
    const int wm = warp >> 2, wn = warp & 3;     // 2 x 4 warp grid, warp tile 64x32
    const int tr = lane >> 2, tc = lane & 3;
    const int row0 = blockIdx.y * 128, col0 = blockIdx.x * 128;
    const int KT = K >> 5;

    float acc[4][4][4];
    #pragma unroll
    for (int i = 0; i < 4; i++)
        #pragma unroll
        for (int j = 0; j < 4; j++)
            #pragma unroll
            for (int r = 0; r < 4; r++) acc[i][j][r] = 0.f;

    auto tile_load = [&](int kt, int buf) {
        int k0 = kt << 5;
        #pragma unroll
        for (int j = 0; j < 4; j++) {
            int L = tid + j * 256;
            int r = L >> 3, c4 = L & 7;
            int soff = buf * 4096 + r * 32 + ((c4 ^ (r & 7)) << 2);
            const float* ga = A + (size_t)(row0 + r) * K + k0 + (c4 << 2);
            uint32_t sa = (uint32_t)__cvta_generic_to_shared(As + soff);
            int sz = (row0 + r < M) ? 16 : 0;
            asm volatile("cp.async.cg.shared.global [%0], [%1], 16, %2;\n"
                         :: "r"(sa), "l"(ga), "r"(sz) : "memory");
            const float* gb = B + (size_t)(col0 + r) * K + k0 + (c4 << 2);
            uint32_t sb = (uint32_t)__cvta_generic_to_shared(Bs + soff);
            asm volatile("cp.async.cg.shared.global [%0], [%1], 16;\n"
                         :: "r"(sb), "l"(gb) : "memory");
        }
        asm volatile("cp.async.commit_group;\n" ::: "memory");
    };

    tile_load(0, 0);
    for (int kt = 0; kt < KT; ++kt) {
        asm volatile("cp.async.wait_group 0;\n" ::: "memory");
        __syncthreads();
        const int cur = kt & 1;
        if (kt + 1 < KT) tile_load(kt + 1, cur ^ 1);
        const float* Ab = As + cur * 4096;
        const float* Bb = Bs + cur * 4096;

        #pragma unroll
        for (int kk = 0; kk < 4; kk++) {
            const int kb = kk << 3;
            uint32_t af[4][4], bf[4][2];
            #pragma unroll
            for (int im = 0; im < 4; im++) {
                int rb = wm * 64 + im * 16;
                int r1 = rb + tr, r2 = rb + tr + 8;
                int k1 = kb + tc, k2 = kb + tc + 4;
                af[im][0] = f2tf32(Ab[r1 * 32 + (((k1 >> 2) ^ (r1 & 7)) << 2) + (k1 & 3)]);
                af[im][1] = f2tf32(Ab[r2 * 32 + (((k1 >> 2) ^ (r2 & 7)) << 2) + (k1 & 3)]);
                af[im][2] = f2tf32(Ab[r1 * 32 + (((k2 >> 2) ^ (r1 & 7)) << 2) + (k2 & 3)]);
                af[im][3] = f2tf32(Ab[r2 * 32 + (((k2 >> 2) ^ (r2 & 7)) << 2) + (k2 & 3)]);
            }
            #pragma unroll
            for (int in = 0; in < 4; in++) {
                int nb = wn * 32 + in * 8 + tr;
                int k1 = kb + tc, k2 = kb + tc + 4;
                bf[in][0] = f2tf32(Bb[nb * 32 + (((k1 >> 2) ^ (nb & 7)) << 2) + (k1 & 3)]);
                bf[in][1] = f2tf32(Bb[nb * 32 + (((k2 >> 2) ^ (nb & 7)) << 2) + (k2 & 3)]);
            }
            #pragma unroll
            for (int im = 0; im < 4; im++)
                #pragma unroll
                for (int in = 0; in < 4; in++)
                    mma_tf32(acc[im][in], af[im], bf[in]);
        }
        __syncthreads();
    }

    // epilogue
    #pragma unroll
    for (int im = 0; im < 4; im++) {
        #pragma unroll
        for (int in = 0; in < 4; in++) {
            #pragma unroll
            for (int h = 0; h < 2; h++) {
                int row = row0 + wm * 64 + im * 16 + tr + h * 8;
                if (row >= M) continue;
                int col = col0 + wn * 32 + in * 8 + (tc << 1);
                float v0 = acc[im][in][h * 2 + 0] + bias[col];
                float v1 = acc[im][in][h * 2 + 1] + bias[col + 1];
                float o0 = v0, o1 = v1;
                if (EPI == 1) {
                    int fi = (col & 127) >> 1;
                    float c = g_ct[row * 64 + fi];
                    float s = g_st[row * 64 + fi];
                    o0 = v0 * c - v1 * s;
                    o1 = v1 * c + v0 * s;
                } else if (EPI == 2) {
                    if (col < DIM) {  // k half gets bucket-center RoPE
                        int a = row & 31;
                        float pos = (a < 16) ? 2.0f : 22.0f;
                        int fi = (col & 127) >> 1;
                        float freq = expf(-(float)fi * (2.0f / 128.0f) * 9.210340371976184f);
                        float s, c;
                        sincosf(pos * freq, &s, &c);
                        o0 = v0 * c - v1 * s;
                        o1 = v1 * c + v0 * s;
                    }
                }
                *reinterpret_cast<float2*>(C + (size_t)row * N + col) = make_float2(o0, o1);
            }
        }
    }
}

// ---------------- attention: per (frame, head), KV len 32 -------------------
__global__ __launch_bounds__(256)
void attn_kernel(const float* __restrict__ q, const float* __restrict__ kv,
                 float* __restrict__ out) {
    __shared__ float kT[128 * 32];      // k transposed: kT[d*32 + a]
    __shared__ float vs[32 * 128];      // v: vs[a*128 + d]
    __shared__ float qb[8][4][128];     // per-warp staged q rows

    const int fh = blockIdx.x;
    const int f = fh / NHEAD, h = fh % NHEAD;
    const int tid = threadIdx.x, lane = tid & 31, warp = tid >> 5;

    const float* kvb = kv + (size_t)f * NA * KVN + h * HD;
    for (int idx = tid; idx < NA * HD; idx += 256) {
        int a = idx >> 7, d = idx & 127;
        kT[d * 32 + a] = kvb[(size_t)a * KVN + d];
        vs[idx] = kvb[(size_t)a * KVN + DIM + d];
    }
    __syncthreads();

    const int sbase = blockIdx.y * 128 + warp * 16;
    for (int g = 0; g < 4; ++g) {
        int s0 = sbase + g * 4;
        #pragma unroll
        for (int r = 0; r < 4; r++) {
            int s = min(s0 + r, S_SP - 1);
            float4 qv = *reinterpret_cast<const float4*>(
                q + (size_t)(f * S_SP + s) * DIM + h * HD + lane * 4);
            *reinterpret_cast<float4*>(&qb[warp][r][lane * 4]) = qv;
        }
        __syncwarp();

        float sc[4] = {0.f, 0.f, 0.f, 0.f};
        #pragma unroll 4
        for (int d = 0; d < 128; d++) {
            float kd = kT[d * 32 + lane];   // lane == kv index a
            #pragma unroll
            for (int r = 0; r < 4; r++) sc[r] = fmaf(qb[warp][r][d], kd, sc[r]);
        }

        float p[4];
        #pragma unroll
        for (int r = 0; r < 4; r++) {
            float x = sc[r] * 0.08838834764831845f;   // 1/sqrt(128)
            float mx = x;
            #pragma unroll
            for (int o = 16; o > 0; o >>= 1) mx = fmaxf(mx, __shfl_xor_sync(0xffffffffu, mx, o));
            float e = expf(x - mx);
            float sum = e;
            #pragma unroll
            for (int o = 16; o > 0; o >>= 1) sum += __shfl_xor_sync(0xffffffffu, sum, o);
            p[r] = e / sum;
        }

        float4 ac[4];
        #pragma unroll
        for (int r = 0; r < 4; r++) ac[r] = make_float4(0.f, 0.f, 0.f, 0.f);
        #pragma unroll
        for (int a = 0; a < 32; a++) {
            float4 va = *reinterpret_cast<const float4*>(&vs[a * 128 + lane * 4]);
            #pragma unroll
            for (int r = 0; r < 4; r++) {
                float pa = __shfl_sync(0xffffffffu, p[r], a);
                ac[r].x = fmaf(pa, va.x, ac[r].x);
                ac[r].y = fmaf(pa, va.y, ac[r].y);
                ac[r].z = fmaf(pa, va.z, ac[r].z);
                ac[r].w = fmaf(pa, va.w, ac[r].w);
            }
        }
        #pragma unroll
        for (int r = 0; r < 4; r++) {
            int s = s0 + r;
            if (s < S_SP)
                *reinterpret_cast<float4*>(
                    out + (size_t)(f * S_SP + s) * DIM + h * HD + lane * 4) = ac[r];
        }
        __syncwarp();
    }
}

// ---------------- launch ----------------
extern "C" void kernel_launch(void* const* d_in, const int* in_sizes, int n_in,
                              void* d_out, int out_size) {
    const float* x      = (const float*)d_in[0];
    const float* enc    = (const float*)d_in[1];
    const float* m      = (const float*)d_in[2];
    const float* q_w    = (const float*)d_in[3];
    const float* q_b    = (const float*)d_in[4];
    const float* kv_w   = (const float*)d_in[5];
    const float* kv_b   = (const float*)d_in[6];
    const float* proj_w = (const float*)d_in[7];
    const float* proj_b = (const float*)d_in[8];
    float* out = (float*)d_out;

    float *qbuf, *kvbuf, *attnbuf;
    cudaGetSymbolAddress((void**)&qbuf, g_q);
    cudaGetSymbolAddress((void**)&kvbuf, g_kv);
    cudaGetSymbolAddress((void**)&attnbuf, g_attn);

    cudaFuncSetAttribute(gemm_tf32<0>, cudaFuncAttributeMaxDynamicSharedMemorySize, SMEM_BYTES);
    cudaFuncSetAttribute(gemm_tf32<1>, cudaFuncAttributeMaxDynamicSharedMemorySize, SMEM_BYTES);
    cudaFuncSetAttribute(gemm_tf32<2>, cudaFuncAttributeMaxDynamicSharedMemorySize, SMEM_BYTES);

    minmax_kernel<<<1, 1024>>>(m, NTS);
    table_kernel<<<(NTS * 64 + 255) / 256, 256>>>(m, NTS);

    // q = x @ q_w^T + q_b, then token RoPE        (M=32760, N=1536, K=1536)
    gemm_tf32<1><<<dim3(DIM / 128, (NTS + 127) / 128), 256, SMEM_BYTES>>>(
        x, q_w, q_b, qbuf, NTS, DIM, DIM);
    // kv = enc @ kv_w^T + kv_b, bucket RoPE on k  (M=672, N=3072, K=768)
    gemm_tf32<2><<<dim3(KVN / 128, (NT * NA + 127) / 128), 256, SMEM_BYTES>>>(
        enc, kv_w, kv_b, kvbuf, NT * NA, KVN, ENC);
    // cross attention
    attn_kernel<<<dim3(NT * NHEAD, 13), 256>>>(qbuf, kvbuf, attnbuf);
    // out = attn @ proj_w^T + proj_b              (M=32760, N=1536, K=1536)
    gemm_tf32<0><<<dim3(DIM / 128, (NTS + 127) / 128), 256, SMEM_BYTES>>>(
        attnbuf, proj_w, proj_b, out, NTS, DIM, DIM);
}

// round 6
// speedup vs baseline: 1.8679x; 1.8679x over previous
#include <cuda_runtime.h>
#include <cuda_fp16.h>
#include <cstdint>
#include <math.h>

// ---------------- problem constants (fixed by setup_inputs) ----------------
#define NT    21
#define S_SP  1560
#define NTS   32760
#define DIM   1536
#define ENC   768
#define NA    32
#define NHEAD 12
#define HD    128
#define KVN   3072

// ---------------- scratch (static device globals) ----------------
__device__ float  g_mm[4];
__device__ float  g_ct[NTS * 64];
__device__ float  g_st[NTS * 64];
__device__ float  g_q[(size_t)NTS * DIM];        // q after GEMM+RoPE (fp32, read by attn)
__device__ float  g_kv[(size_t)NT * NA * KVN];   // kv after GEMM (fp32)
__device__ __half g_xh[(size_t)NTS * DIM];       // x in fp16
__device__ __half g_qwh[(size_t)DIM * DIM];      // q_w in fp16
__device__ __half g_pwh[(size_t)DIM * DIM];      // proj_w in fp16
__device__ __half g_attnh[(size_t)NTS * DIM];    // attention output in fp16

// ---------------- fp32 -> fp16 conversion ----------------
__global__ void f2h_kernel(const float* __restrict__ in, __half* __restrict__ out, long n4) {
    long i = (long)blockIdx.x * blockDim.x + threadIdx.x;
    if (i >= n4) return;
    float4 v = reinterpret_cast<const float4*>(in)[i];
    __half2 h0 = __floats2half2_rn(v.x, v.y);
    __half2 h1 = __floats2half2_rn(v.z, v.w);
    uint2 o;
    o.x = *reinterpret_cast<uint32_t*>(&h0);
    o.y = *reinterpret_cast<uint32_t*>(&h1);
    reinterpret_cast<uint2*>(out)[i] = o;
}

// ---------------- min/max of the two attn-map rows ----------------
__global__ void minmax_kernel(const float* __restrict__ m, int n) {
    const int tid = threadIdx.x, lane = tid & 31, warp = tid >> 5;
    float mn0 = 1e30f, mx0 = -1e30f, mn1 = 1e30f, mx1 = -1e30f;
    for (int i = tid; i < n; i += blockDim.x) {
        float a = m[i], b = m[n + i];
        mn0 = fminf(mn0, a); mx0 = fmaxf(mx0, a);
        mn1 = fminf(mn1, b); mx1 = fmaxf(mx1, b);
    }
    #pragma unroll
    for (int o = 16; o > 0; o >>= 1) {
        mn0 = fminf(mn0, __shfl_xor_sync(0xffffffffu, mn0, o));
        mx0 = fmaxf(mx0, __shfl_xor_sync(0xffffffffu, mx0, o));
        mn1 = fminf(mn1, __shfl_xor_sync(0xffffffffu, mn1, o));
        mx1 = fmaxf(mx1, __shfl_xor_sync(0xffffffffu, mx1, o));
    }
    __shared__ float s0[32], s1[32], s2[32], s3[32];
    if (lane == 0) { s0[warp] = mn0; s1[warp] = mx0; s2[warp] = mn1; s3[warp] = mx1; }
    __syncthreads();
    if (warp == 0) {
        int nw = blockDim.x >> 5;
        mn0 = (lane < nw) ? s0[lane] : 1e30f;
        mx0 = (lane < nw) ? s1[lane] : -1e30f;
        mn1 = (lane < nw) ? s2[lane] : 1e30f;
        mx1 = (lane < nw) ? s3[lane] : -1e30f;
        #pragma unroll
        for (int o = 16; o > 0; o >>= 1) {
            mn0 = fminf(mn0, __shfl_xor_sync(0xffffffffu, mn0, o));
            mx0 = fmaxf(mx0, __shfl_xor_sync(0xffffffffu, mx0, o));
            mn1 = fminf(mn1, __shfl_xor_sync(0xffffffffu, mn1, o));
            mx1 = fmaxf(mx1, __shfl_xor_sync(0xffffffffu, mx1, o));
        }
        if (lane == 0) { g_mm[0] = mn0; g_mm[1] = mx0; g_mm[2] = mn1; g_mm[3] = mx1; }
    }
}

// ---------------- per-(token,freq) cos/sin table ----------------
__global__ void table_kernel(const float* __restrict__ m, int n) {
    int idx = blockIdx.x * blockDim.x + threadIdx.x;
    if (idx >= n * 64) return;
    int t = idx >> 6, i = idx & 63;
    float mn0 = g_mm[0], mx0 = g_mm[1], mn1 = g_mm[2], mx1 = g_mm[3];
    float m0 = m[t], m1 = m[n + t];
    float h1 = (m0 - mn0) / (mx0 - mn0 + 1e-8f) * 4.0f;
    float h2 = (m1 - mn1) / (mx1 - mn1 + 1e-8f) * 4.0f + 20.0f;
    float pos = (m0 >= m1) ? h1 : h2;
    float freq = expf(-(float)i * (2.0f / 128.0f) * 9.210340371976184f);
    float s, c;
    sincosf(pos * freq, &s, &c);
    g_ct[idx] = c;
    g_st[idx] = s;
}

// ---------------- fp16 GEMM: C[M,1536] = A[M,1536] @ B[1536,1536]^T + bias --
// ldmatrix + mma.m16n8k16, 128x128 block tile, BK=64, 3-stage cp.async.
// EPI: 0 = bias only, 1 = bias + per-token RoPE from tables
#define HBK 64
#define HSTAGE_BYTES (128 * HBK * 2 * 2)      // A tile 16KB + B tile 16KB
#define HSTAGES 3
#define SMEM_H (HSTAGES * HSTAGE_BYTES)       // 98304
#define HKT (1536 / HBK)                      // 24

__device__ __forceinline__ void mma16816(float* d, const uint32_t* a, const uint32_t* b) {
    asm volatile(
        "mma.sync.aligned.m16n8k16.row.col.f32.f16.f16.f32 "
        "{%0,%1,%2,%3}, {%4,%5,%6,%7}, {%8,%9}, {%0,%1,%2,%3};\n"
        : "+f"(d[0]), "+f"(d[1]), "+f"(d[2]), "+f"(d[3])
        : "r"(a[0]), "r"(a[1]), "r"(a[2]), "r"(a[3]), "r"(b[0]), "r"(b[1]));
}
__device__ __forceinline__ void ldsm4(uint32_t* r, uint32_t addr) {
    asm volatile("ldmatrix.sync.aligned.m8n8.x4.shared.b16 {%0,%1,%2,%3}, [%4];"
                 : "=r"(r[0]), "=r"(r[1]), "=r"(r[2]), "=r"(r[3]) : "r"(addr));
}

template <int EPI>
__global__ __launch_bounds__(256)
void gemm_h(const __half* __restrict__ A, const __half* __restrict__ B,
            const float* __restrict__ bias, float* __restrict__ C, int M) {
    extern __shared__ char sm[];
    const int tid = threadIdx.x, lane = tid & 31, warp = tid >> 5;
    const int wm = warp >> 2, wn = warp & 3;         // 2 x 4 warps, warp tile 64x32
    const int row0 = blockIdx.y * 128, col0 = blockIdx.x * 128;

    float acc[4][4][4];
    #pragma unroll
    for (int i = 0; i < 4; i++)
        #pragma unroll
        for (int j = 0; j < 4; j++)
            #pragma unroll
            for (int r = 0; r < 4; r++) acc[i][j][r] = 0.f;

    // ---- stage loader: 4 A-chunks + 4 B-chunks of 16B per thread ----
    auto load_stage = [&](int kt, int s) {
        const int k0 = kt * HBK;
        char* base = sm + s * HSTAGE_BYTES;
        #pragma unroll
        for (int j = 0; j < 4; j++) {
            int id = tid + j * 256;
            int r = id >> 3, c = id & 7;
            int phys = (c ^ (r & 7)) << 4;
            uint32_t sa = (uint32_t)__cvta_generic_to_shared(base + r * 128 + phys);
            const __half* ga = A + (size_t)(row0 + r) * 1536 + k0 + c * 8;
            int sz = (row0 + r < M) ? 16 : 0;
            asm volatile("cp.async.cg.shared.global [%0], [%1], 16, %2;\n"
                         :: "r"(sa), "l"(ga), "r"(sz) : "memory");
            uint32_t sb = (uint32_t)__cvta_generic_to_shared(base + 16384 + r * 128 + phys);
            const __half* gb = B + (size_t)(col0 + r) * 1536 + k0 + c * 8;
            asm volatile("cp.async.cg.shared.global [%0], [%1], 16;\n"
                         :: "r"(sb), "l"(gb) : "memory");
        }
        asm volatile("cp.async.commit_group;\n" ::: "memory");
    };

    load_stage(0, 0);
    load_stage(1, 1);

    const int lrow = lane & 15;      // row within a 16-row ldmatrix tile
    const int lkh  = lane >> 4;      // 0/1 -> k-halves 0-7 / 8-15

    for (int kt = 0; kt < HKT; kt++) {
        if (kt < HKT - 1) { asm volatile("cp.async.wait_group 1;\n" ::: "memory"); }
        else              { asm volatile("cp.async.wait_group 0;\n" ::: "memory"); }
        __syncthreads();
        if (kt + 2 < HKT) load_stage(kt + 2, (kt + 2) % HSTAGES);

        const char* Ab = sm + (kt % HSTAGES) * HSTAGE_BYTES;
        const char* Bb = Ab + 16384;

        #pragma unroll
        for (int kk = 0; kk < 4; kk++) {
            const int cbase = kk * 2 + lkh;              // 16B-chunk index in row
            uint32_t af[4][4], bf[4][2];
            #pragma unroll
            for (int im = 0; im < 4; im++) {
                int r = wm * 64 + im * 16 + lrow;
                uint32_t addr = (uint32_t)__cvta_generic_to_shared(
                    Ab + r * 128 + ((cbase ^ (r & 7)) << 4));
                ldsm4(af[im], addr);
            }
            #pragma unroll
            for (int i2 = 0; i2 < 2; i2++) {
                int r = wn * 32 + i2 * 16 + lrow;
                uint32_t addr = (uint32_t)__cvta_generic_to_shared(
                    Bb + r * 128 + ((cbase ^ (r & 7)) << 4));
                uint32_t t[4];
                ldsm4(t, addr);
                bf[i2 * 2][0] = t[0]; bf[i2 * 2][1] = t[2];
                bf[i2 * 2 + 1][0] = t[1]; bf[i2 * 2 + 1][1] = t[3];
            }
            #pragma unroll
            for (int im = 0; im < 4; im++)
                #pragma unroll
                for (int in = 0; in < 4; in++)
                    mma16816(acc[im][in], af[im], bf[in]);
        }
        __syncthreads();
    }

    // ---- epilogue: bias (+ RoPE), fp32 stores ----
    const int tr = lane >> 2, tc = lane & 3;
    #pragma unroll
    for (int im = 0; im < 4; im++)
        #pragma unroll
        for (int in = 0; in < 4; in++)
            #pragma unroll
            for (int h = 0; h < 2; h++) {
                int row = row0 + wm * 64 + im * 16 + tr + h * 8;
                if (row >= M) continue;
                int col = col0 + wn * 32 + in * 8 + (tc << 1);
                float v0 = acc[im][in][h * 2 + 0] + bias[col];
                float v1 = acc[im][in][h * 2 + 1] + bias[col + 1];
                if (EPI == 1) {
                    int fi = (col & 127) >> 1;
                    float cc = g_ct[row * 64 + fi], ss = g_st[row * 64 + fi];
                    float a = v0, b = v1;
                    v0 = a * cc - b * ss;
                    v1 = b * cc + a * ss;
                }
                *reinterpret_cast<float2*>(C + (size_t)row * DIM + col) = make_float2(v0, v1);
            }
}

// ---------------- SIMT TF32 GEMM for the small kv projection ----------------
__device__ __forceinline__ uint32_t f2tf32(float f) {
    uint32_t r;
    asm("cvt.rna.tf32.f32 %0, %1;" : "=r"(r) : "f"(f));
    return r;
}
__device__ __forceinline__ void mma_tf32(float* d, const uint32_t* a, const uint32_t* b) {
    asm volatile(
        "mma.sync.aligned.m16n8k8.row.col.f32.tf32.tf32.f32 "
        "{%0,%1,%2,%3}, {%4,%5,%6,%7}, {%8,%9}, {%0,%1,%2,%3};\n"
        : "+f"(d[0]), "+f"(d[1]), "+f"(d[2]), "+f"(d[3])
        : "r"(a[0]), "r"(a[1]), "r"(a[2]), "r"(a[3]), "r"(b[0]), "r"(b[1]));
}
#define SMEM_KV (2 * 2 * 128 * 32 * 4)

__global__ __launch_bounds__(256)
void gemm_kv(const float* __restrict__ A, const float* __restrict__ B,
             const float* __restrict__ bias, float* __restrict__ C,
             int M, int N, int K) {
    extern __shared__ float smf[];
    float* As = smf;
    float* Bs = smf + 2 * 4096;
    const int tid = threadIdx.x, lane = tid & 31, warp = tid >> 5;
    const int wm = warp >> 2, wn = warp & 3;
    const int tr = lane >> 2, tc = lane & 3;
    const int row0 = blockIdx.y * 128, col0 = blockIdx.x * 128;
    const int KT = K >> 5;

    float acc[4][4][4];
    #pragma unroll
    for (int i = 0; i < 4; i++)
        #pragma unroll
        for (int j = 0; j < 4; j++)
            #pragma unroll
            for (int r = 0; r < 4; r++) acc[i][j][r] = 0.f;

    auto tile_load = [&](int kt, int buf) {
        int k0 = kt << 5;
        #pragma unroll
        for (int j = 0; j < 4; j++) {
            int L = tid + j * 256;
            int r = L >> 3, c4 = L & 7;
            int soff = buf * 4096 + r * 32 + ((c4 ^ (r & 7)) << 2);
            const float* ga = A + (size_t)(row0 + r) * K + k0 + (c4 << 2);
            uint32_t sa = (uint32_t)__cvta_generic_to_shared(As + soff);
            int sz = (row0 + r < M) ? 16 : 0;
            asm volatile("cp.async.cg.shared.global [%0], [%1], 16, %2;\n"
                         :: "r"(sa), "l"(ga), "r"(sz) : "memory");
            const float* gb = B + (size_t)(col0 + r) * K + k0 + (c4 << 2);
            uint32_t sb = (uint32_t)__cvta_generic_to_shared(Bs + soff);
            asm volatile("cp.async.cg.shared.global [%0], [%1], 16;\n"
                         :: "r"(sb), "l"(gb) : "memory");
        }
        asm volatile("cp.async.commit_group;\n" ::: "memory");
    };

    tile_load(0, 0);
    for (int kt = 0; kt < KT; ++kt) {
        asm volatile("cp.async.wait_group 0;\n" ::: "memory");
        __syncthreads();
        const int cur = kt & 1;
        if (kt + 1 < KT) tile_load(kt + 1, cur ^ 1);
        const float* Ab = As + cur * 4096;
        const float* Bb = Bs + cur * 4096;
        #pragma unroll
        for (int kk = 0; kk < 4; kk++) {
            const int kb = kk << 3;
            uint32_t af[4][4], bf[4][2];
            #pragma unroll
            for (int im = 0; im < 4; im++) {
                int rb = wm * 64 + im * 16;
                int r1 = rb + tr, r2 = rb + tr + 8;
                int k1 = kb + tc, k2 = kb + tc + 4;
                af[im][0] = f2tf32(Ab[r1 * 32 + (((k1 >> 2) ^ (r1 & 7)) << 2) + (k1 & 3)]);
                af[im][1] = f2tf32(Ab[r2 * 32 + (((k1 >> 2) ^ (r2 & 7)) << 2) + (k1 & 3)]);
                af[im][2] = f2tf32(Ab[r1 * 32 + (((k2 >> 2) ^ (r1 & 7)) << 2) + (k2 & 3)]);
                af[im][3] = f2tf32(Ab[r2 * 32 + (((k2 >> 2) ^ (r2 & 7)) << 2) + (k2 & 3)]);
            }
            #pragma unroll
            for (int in = 0; in < 4; in++) {
                int nb = wn * 32 + in * 8 + tr;
                int k1 = kb + tc, k2 = kb + tc + 4;
                bf[in][0] = f2tf32(Bb[nb * 32 + (((k1 >> 2) ^ (nb & 7)) << 2) + (k1 & 3)]);
                bf[in][1] = f2tf32(Bb[nb * 32 + (((k2 >> 2) ^ (nb & 7)) << 2) + (k2 & 3)]);
            }
            #pragma unroll
            for (int im = 0; im < 4; im++)
                #pragma unroll
                for (int in = 0; in < 4; in++)
                    mma_tf32(acc[im][in], af[im], bf[in]);
        }
        __syncthreads();
    }

    #pragma unroll
    for (int im = 0; im < 4; im++)
        #pragma unroll
        for (int in = 0; in < 4; in++)
            #pragma unroll
            for (int h = 0; h < 2; h++) {
                int row = row0 + wm * 64 + im * 16 + tr + h * 8;
                if (row >= M) continue;
                int col = col0 + wn * 32 + in * 8 + (tc << 1);
                float v0 = acc[im][in][h * 2 + 0] + bias[col];
                float v1 = acc[im][in][h * 2 + 1] + bias[col + 1];
                if (col < DIM) {   // k half: bucket-centre RoPE
                    int a = row & 31;
                    float pos = (a < 16) ? 2.0f : 22.0f;
                    int fi = (col & 127) >> 1;
                    float freq = expf(-(float)fi * (2.0f / 128.0f) * 9.210340371976184f);
                    float s, c;
                    sincosf(pos * freq, &s, &c);
                    float o0 = v0 * c - v1 * s;
                    float o1 = v1 * c + v0 * s;
                    v0 = o0; v1 = o1;
                }
                *reinterpret_cast<float2*>(C + (size_t)row * N + col) = make_float2(v0, v1);
            }
}

// ---------------- attention: per (frame, head), KV len 32; fp16 output ------
__global__ __launch_bounds__(256)
void attn_kernel(const float* __restrict__ q, const float* __restrict__ kv,
                 __half* __restrict__ out) {
    __shared__ float kT[128 * 32];
    __shared__ float vs[32 * 128];
    __shared__ float qb[8][4][128];

    const int fh = blockIdx.x;
    const int f = fh / NHEAD, h = fh % NHEAD;
    const int tid = threadIdx.x, lane = tid & 31, warp = tid >> 5;

    const float* kvb = kv + (size_t)f * NA * KVN + h * HD;
    for (int idx = tid; idx < NA * HD; idx += 256) {
        int a = idx >> 7, d = idx & 127;
        kT[d * 32 + a] = kvb[(size_t)a * KVN + d];
        vs[idx] = kvb[(size_t)a * KVN + DIM + d];
    }
    __syncthreads();

    const int sbase = blockIdx.y * 128 + warp * 16;
    for (int g = 0; g < 4; ++g) {
        int s0 = sbase + g * 4;
        #pragma unroll
        for (int r = 0; r < 4; r++) {
            int s = min(s0 + r, S_SP - 1);
            float4 qv = *reinterpret_cast<const float4*>(
                q + (size_t)(f * S_SP + s) * DIM + h * HD + lane * 4);
            *reinterpret_cast<float4*>(&qb[warp][r][lane * 4]) = qv;
        }
        __syncwarp();

        float sc[4] = {0.f, 0.f, 0.f, 0.f};
        #pragma unroll 4
        for (int d = 0; d < 128; d++) {
            float kd = kT[d * 32 + lane];
            #pragma unroll
            for (int r = 0; r < 4; r++) sc[r] = fmaf(qb[warp][r][d], kd, sc[r]);
        }

        float p[4];
        #pragma unroll
        for (int r = 0; r < 4; r++) {
            float x = sc[r] * 0.08838834764831845f;
            float mx = x;
            #pragma unroll
            for (int o = 16; o > 0; o >>= 1) mx = fmaxf(mx, __shfl_xor_sync(0xffffffffu, mx, o));
            float e = expf(x - mx);
            float sum = e;
            #pragma unroll
            for (int o = 16; o > 0; o >>= 1) sum += __shfl_xor_sync(0xffffffffu, sum, o);
            p[r] = e / sum;
        }

        float4 ac[4];
        #pragma unroll
        for (int r = 0; r < 4; r++) ac[r] = make_float4(0.f, 0.f, 0.f, 0.f);
        #pragma unroll
        for (int a = 0; a < 32; a++) {
            float4 va = *reinterpret_cast<const float4*>(&vs[a * 128 + lane * 4]);
            #pragma unroll
            for (int r = 0; r < 4; r++) {
                float pa = __shfl_sync(0xffffffffu, p[r], a);
                ac[r].x = fmaf(pa, va.x, ac[r].x);
                ac[r].y = fmaf(pa, va.y, ac[r].y);
                ac[r].z = fmaf(pa, va.z, ac[r].z);
                ac[r].w = fmaf(pa, va.w, ac[r].w);
            }
        }
        #pragma unroll
        for (int r = 0; r < 4; r++) {
            int s = s0 + r;
            if (s < S_SP) {
                __half2 h0 = __floats2half2_rn(ac[r].x, ac[r].y);
                __half2 h1 = __floats2half2_rn(ac[r].z, ac[r].w);
                uint2 o;
                o.x = *reinterpret_cast<uint32_t*>(&h0);
                o.y = *reinterpret_cast<uint32_t*>(&h1);
                *reinterpret_cast<uint2*>(
                    out + (size_t)(f * S_SP + s) * DIM + h * HD + lane * 4) = o;
            }
        }
        __syncwarp();
    }
}

// ---------------- launch ----------------
extern "C" void kernel_launch(void* const* d_in, const int* in_sizes, int n_in,
                              void* d_out, int out_size) {
    const float* x      = (const float*)d_in[0];
    const float* enc    = (const float*)d_in[1];
    const float* m      = (const float*)d_in[2];
    const float* q_w    = (const float*)d_in[3];
    const float* q_b    = (const float*)d_in[4];
    const float* kv_w   = (const float*)d_in[5];
    const float* kv_b   = (const float*)d_in[6];
    const float* proj_w = (const float*)d_in[7];
    const float* proj_b = (const float*)d_in[8];
    float* out = (float*)d_out;

    float *qbuf, *kvbuf;
    __half *xh, *qwh, *pwh, *attnh;
    cudaGetSymbolAddress((void**)&qbuf, g_q);
    cudaGetSymbolAddress((void**)&kvbuf, g_kv);
    cudaGetSymbolAddress((void**)&xh, g_xh);
    cudaGetSymbolAddress((void**)&qwh, g_qwh);
    cudaGetSymbolAddress((void**)&pwh, g_pwh);
    cudaGetSymbolAddress((void**)&attnh, g_attnh);

    cudaFuncSetAttribute(gemm_h<0>, cudaFuncAttributeMaxDynamicSharedMemorySize, SMEM_H);
    cudaFuncSetAttribute(gemm_h<1>, cudaFuncAttributeMaxDynamicSharedMemorySize, SMEM_H);
    cudaFuncSetAttribute(gemm_kv, cudaFuncAttributeMaxDynamicSharedMemorySize, SMEM_KV);

    minmax_kernel<<<1, 1024>>>(m, NTS);
    table_kernel<<<(NTS * 64 + 255) / 256, 256>>>(m, NTS);

    // fp16 operand preparation
    long nx4 = (long)NTS * DIM / 4, nw4 = (long)DIM * DIM / 4;
    f2h_kernel<<<(unsigned)((nx4 + 255) / 256), 256>>>(x, xh, nx4);
    f2h_kernel<<<(unsigned)((nw4 + 255) / 256), 256>>>(q_w, qwh, nw4);
    f2h_kernel<<<(unsigned)((nw4 + 255) / 256), 256>>>(proj_w, pwh, nw4);

    // q = x @ q_w^T + q_b, fused token RoPE   (fp16 tensor cores)
    gemm_h<1><<<dim3(DIM / 128, (NTS + 127) / 128), 256, SMEM_H>>>(
        xh, qwh, q_b, qbuf, NTS);
    // kv = enc @ kv_w^T + kv_b, bucket RoPE on k half (fp32 SIMT; tiny)
    gemm_kv<<<dim3(KVN / 128, (NT * NA + 127) / 128), 256, SMEM_KV>>>(
        enc, kv_w, kv_b, kvbuf, NT * NA, KVN, ENC);
    // cross attention (fp16 output)
    attn_kernel<<<dim3(NT * NHEAD, 13), 256>>>(qbuf, kvbuf, attnh);
    // out = attn @ proj_w^T + proj_b          (fp16 tensor cores)
    gemm_h<0><<<dim3(DIM / 128, (NTS + 127) / 128), 256, SMEM_H>>>(
        attnh, pwh, proj_b, out, NTS);
}